// round 9
// baseline (speedup 1.0000x reference)
#include <cuda_runtime.h>
#include <cuda_fp16.h>
#include <cstdint>

// Problem: B=8, C=256, H=W=64, O=256, K=3, E=3
// Winograd F(2x2,3x3):
//   U[b][f][o][c] = G * w2[b,o,c] * G^T           (fp16, f=0..15)
//   V[b][f][t][c] = B^T * d(tile t) * B           (fp16, t=0..1023)
//   M[b][f][o][t] = sum_c U * V                   (fp16 GEMM, f32 acc)
//   out 2x2 per tile = A^T * M * A
// 16 GEMMs/batch of 256x1024x256: 4.19M HMMA vs 9.44M direct (2.25x cut).

#define BQ 8
#define CQ 256
#define HQ 64
#define WQ 64
#define OQ 256

__device__ float  g_yctx[BQ * CQ];
__device__ float  g_gates[BQ * 3];
__device__ __half g_U[(size_t)BQ * 16 * OQ * CQ];       // [b][f][o][c]
__device__ __half g_V[(size_t)BQ * 16 * 1024 * CQ];     // [b][f][t][c]
__device__ __half g_M[(size_t)BQ * 16 * OQ * 1024];     // [b][f][o][t]

__device__ __forceinline__ uint32_t smem_u32(const void* p) {
    uint32_t a;
    asm("{ .reg .u64 t; cvta.to.shared.u64 t, %1; cvt.u32.u64 %0, t; }" : "=r"(a) : "l"(p));
    return a;
}

// ---------------------------------------------------------------------------
// Kernel 1: global average pool of y -> g_yctx
// ---------------------------------------------------------------------------
__global__ void k_mean(const float* __restrict__ y) {
    int bc = blockIdx.x;
    const float* p = y + (size_t)bc * (HQ * WQ);
    float s = 0.f;
    for (int i = threadIdx.x; i < HQ * WQ; i += 256) s += p[i];
    __shared__ float sm[256];
    sm[threadIdx.x] = s;
    __syncthreads();
    for (int st = 128; st > 0; st >>= 1) {
        if (threadIdx.x < st) sm[threadIdx.x] += sm[threadIdx.x + st];
        __syncthreads();
    }
    if (threadIdx.x == 0) g_yctx[bc] = sm[0] * (1.f / (HQ * WQ));
}

// ---------------------------------------------------------------------------
// Kernel 2: softmax gates
// ---------------------------------------------------------------------------
__global__ void k_gates(const float* __restrict__ gw, const float* __restrict__ gb) {
    int b = blockIdx.x;
    int c = threadIdx.x;
    float v = g_yctx[b * CQ + c];
    float p0 = v * (gw[c * 3 + 0] + gw[(c + CQ) * 3 + 0]);
    float p1 = v * (gw[c * 3 + 1] + gw[(c + CQ) * 3 + 1]);
    float p2 = v * (gw[c * 3 + 2] + gw[(c + CQ) * 3 + 2]);
    __shared__ float sm[3][256];
    sm[0][c] = p0; sm[1][c] = p1; sm[2][c] = p2;
    __syncthreads();
    for (int st = 128; st > 0; st >>= 1) {
        if (c < st) {
            sm[0][c] += sm[0][c + st];
            sm[1][c] += sm[1][c + st];
            sm[2][c] += sm[2][c + st];
        }
        __syncthreads();
    }
    if (c == 0) {
        float l0 = sm[0][0] + gb[0], l1 = sm[1][0] + gb[1], l2 = sm[2][0] + gb[2];
        float m = fmaxf(l0, fmaxf(l1, l2));
        float e0 = expf(l0 - m), e1 = expf(l1 - m), e2 = expf(l2 - m);
        float inv = 1.f / (e0 + e1 + e2);
        g_gates[b * 3 + 0] = e0 * inv;
        g_gates[b * 3 + 1] = e1 * inv;
        g_gates[b * 3 + 2] = e2 * inv;
    }
}

// ---------------------------------------------------------------------------
// Kernel 3: fold experts + Winograd weight transform -> U[b][f][o][c] fp16
// block = o (256 blocks), 256 threads = c
// ---------------------------------------------------------------------------
__global__ void k_foldU(const float* __restrict__ experts) {
    int o = blockIdx.x;
    int c = threadIdx.x;
    const size_t ES = (size_t)OQ * (2 * CQ) * 9;
    float f3[3][9];
#pragma unroll
    for (int e = 0; e < 3; e++) {
        const float* p = experts + e * ES + (size_t)o * (2 * CQ * 9) + (size_t)c * 9;
#pragma unroll
        for (int t = 0; t < 9; t++) f3[e][t] = p[t] + p[CQ * 9 + t];
    }
#pragma unroll
    for (int b = 0; b < BQ; b++) {
        float g0 = g_gates[b * 3 + 0];
        float g1 = g_gates[b * 3 + 1];
        float g2 = g_gates[b * 3 + 2];
        float w[3][3];
#pragma unroll
        for (int t = 0; t < 9; t++)
            w[t / 3][t % 3] = g0 * f3[0][t] + g1 * f3[1][t] + g2 * f3[2][t];
        // T = G w  (4x3)
        float T[4][3];
#pragma unroll
        for (int j = 0; j < 3; j++) {
            T[0][j] = w[0][j];
            T[1][j] = 0.5f * (w[0][j] + w[1][j] + w[2][j]);
            T[2][j] = 0.5f * (w[0][j] - w[1][j] + w[2][j]);
            T[3][j] = w[2][j];
        }
        __half* ub = g_U + ((size_t)b * 16 * OQ + o) * CQ + c;   // +f*OQ*CQ
#pragma unroll
        for (int r = 0; r < 4; r++) {
            float u0 = T[r][0];
            float u1 = 0.5f * (T[r][0] + T[r][1] + T[r][2]);
            float u2 = 0.5f * (T[r][0] - T[r][1] + T[r][2]);
            float u3 = T[r][2];
            ub[(size_t)(r * 4 + 0) * OQ * CQ] = __float2half_rn(u0);
            ub[(size_t)(r * 4 + 1) * OQ * CQ] = __float2half_rn(u1);
            ub[(size_t)(r * 4 + 2) * OQ * CQ] = __float2half_rn(u2);
            ub[(size_t)(r * 4 + 3) * OQ * CQ] = __float2half_rn(u3);
        }
    }
}

// ---------------------------------------------------------------------------
// Kernel 4: input transform q -> V[b][f][t][c] fp16.
// block = (b, ty): 256 threads. Loop c-chunks of 32.
// sQ[32c][4r][66x] f32 (plane padded to 265 words -> conflict-free lane=c),
// sVt[16f][32tx][32c] fp16 restage for coalesced output.
// ---------------------------------------------------------------------------
#define TQ_SQW 265                          // padded plane stride (words)
#define TQ_SQ_BYTES (32 * TQ_SQW * 4)       // 33920
#define TQ_VT_OFF TQ_SQ_BYTES
#define TQ_SMEM (TQ_SQ_BYTES + 16 * 32 * 32 * 2)   // 33920 + 32768 = 66688

__global__ __launch_bounds__(256) void k_trans(const float* __restrict__ q) {
    extern __shared__ __align__(16) unsigned char smt[];
    float*  sQ  = (float*)smt;
    __half* sVt = (__half*)(smt + TQ_VT_OFF);

    int ty = blockIdx.x;        // 0..31
    int b  = blockIdx.y;
    int tid = threadIdx.x;

    const float* qb = q + (size_t)b * CQ * HQ * WQ;

    for (int cc = 0; cc < 8; cc++) {
        int c0 = cc * 32;
        __syncthreads();   // prior iteration's smem reads done

        // ---- stage q[c0..+31][2ty-1..2ty+2][-1..64] ----
        for (int i = tid; i < 32 * 264; i += 256) {
            int c   = i / 264;
            int rem = i - c * 264;
            int r   = rem / 66;
            int x   = rem - r * 66 - 1;
            int gy  = 2 * ty - 1 + r;
            float v = 0.f;
            if ((unsigned)gy < (unsigned)HQ && (unsigned)x < (unsigned)WQ)
                v = qb[(size_t)(c0 + c) * (HQ * WQ) + gy * WQ + x];
            sQ[c * TQ_SQW + rem] = v;
        }
        __syncthreads();

        // ---- transform: each thread 4 (tx,c) items ----
#pragma unroll
        for (int jj = 0; jj < 4; jj++) {
            int j  = jj * 256 + tid;
            int c  = j & 31;
            int tx = j >> 5;
            const float* dp = sQ + c * TQ_SQW + 2 * tx;   // + r*66 + jx
            float d[4][4];
#pragma unroll
            for (int r = 0; r < 4; r++)
#pragma unroll
                for (int jx = 0; jx < 4; jx++)
                    d[r][jx] = dp[r * 66 + jx];
            float T[4][4];
#pragma unroll
            for (int jx = 0; jx < 4; jx++) {
                T[0][jx] = d[0][jx] - d[2][jx];
                T[1][jx] = d[1][jx] + d[2][jx];
                T[2][jx] = d[2][jx] - d[1][jx];
                T[3][jx] = d[1][jx] - d[3][jx];
            }
#pragma unroll
            for (int r = 0; r < 4; r++) {
                float v0 = T[r][0] - T[r][2];
                float v1 = T[r][1] + T[r][2];
                float v2 = T[r][2] - T[r][1];
                float v3 = T[r][1] - T[r][3];
                sVt[((r * 4 + 0) * 32 + tx) * 32 + c] = __float2half_rn(v0);
                sVt[((r * 4 + 1) * 32 + tx) * 32 + c] = __float2half_rn(v1);
                sVt[((r * 4 + 2) * 32 + tx) * 32 + c] = __float2half_rn(v2);
                sVt[((r * 4 + 3) * 32 + tx) * 32 + c] = __float2half_rn(v3);
            }
        }
        __syncthreads();

        // ---- coalesced write: 2048 uint4 ----
#pragma unroll
        for (int k = 0; k < 8; k++) {
            int u   = tid + k * 256;         // 0..2047
            int f   = u >> 7;
            int rem = u & 127;
            int tx  = rem >> 2;
            int uq  = rem & 3;
            uint4 v = *(const uint4*)(sVt + (f * 32 + tx) * 32 + uq * 8);
            __half* dst = g_V + (((size_t)(b * 16 + f) * 1024) + ty * 32 + tx) * CQ
                        + c0 + uq * 8;
            *(uint4*)dst = v;
        }
    }
}

// ---------------------------------------------------------------------------
// Kernel 5: 16 GEMMs/batch, M[o][t] = sum_c U[o][c] V[t][c].
// grid (8 tblk, 2 ohalf, b*16+f). CTA 128x128, 128 thr, warps 2Mx2N (64x64).
// K=256 in 4 chunks of 64; A/B chunk tiles 16KB each, 3-stage cp.async.
// Rows 128B, swizzle: phys_u = u ^ (row & 7).
// ---------------------------------------------------------------------------
#define WG_STAGE 32768                      // A 16384 + B 16384
#define WG_SMEM  (3 * WG_STAGE)             // 98304

__global__ __launch_bounds__(128, 2)
void k_wgemm() {
    extern __shared__ __align__(16) unsigned char smg[];
    const uint32_t sb = smem_u32(smg);

    int tid  = threadIdx.x;
    int lane = tid & 31;
    int warp = tid >> 5;
    int wm   = warp >> 1;       // 0..1
    int wn   = warp & 1;        // 0..1

    int t0 = blockIdx.x * 128;
    int o0 = blockIdx.y * 128;
    int bf = blockIdx.z;        // b*16+f

    const __half* Aq = g_U + ((size_t)bf * OQ + o0) * CQ;
    const __half* Bq = g_V + ((size_t)bf * 1024 + t0) * CQ;

    auto load_chunk = [&](int kk, int stg) {
#pragma unroll
        for (int g = 0; g < 16; g++) {
            int idx  = tid + g * 128;       // 0..2047
            int part = idx >> 10;
            int rem  = idx & 1023;
            int row  = rem >> 3;
            int u    = rem & 7;
            const __half* src = (part ? Bq : Aq) + (size_t)row * CQ + kk * 64 + u * 8;
            uint32_t dst = sb + stg * WG_STAGE + part * 16384 + row * 128
                         + ((u ^ (row & 7)) << 4);
            asm volatile("cp.async.cg.shared.global [%0], [%1], 16;"
                         :: "r"(dst), "l"(src));
        }
        asm volatile("cp.async.commit_group;");
    };

    float acc[4][8][4];
#pragma unroll
    for (int i = 0; i < 4; i++)
#pragma unroll
        for (int j = 0; j < 8; j++)
#pragma unroll
            for (int k = 0; k < 4; k++) acc[i][j][k] = 0.f;

    int tg = lane & 3;
    int g8 = lane >> 2;

    load_chunk(0, 0);
    load_chunk(1, 1);
    load_chunk(2, 2);

    for (int kk = 0; kk < 4; kk++) {
        if (kk < 2)       asm volatile("cp.async.wait_group 2;");
        else if (kk == 2) asm volatile("cp.async.wait_group 1;");
        else              asm volatile("cp.async.wait_group 0;");
        __syncthreads();

        uint32_t aBuf = sb + (kk % 3) * WG_STAGE;
        uint32_t bBuf = aBuf + 16384;

#pragma unroll
        for (int k16 = 0; k16 < 4; k16++) {
            uint32_t a[4][4];
#pragma unroll
            for (int fm = 0; fm < 4; fm++) {
                int row = wm * 64 + fm * 16 + (lane & 15);
                int u   = (lane >> 4) + 2 * k16;
                uint32_t addr = aBuf + row * 128 + ((u ^ (row & 7)) << 4);
                asm volatile(
                    "ldmatrix.sync.aligned.m8n8.x4.shared.b16 {%0,%1,%2,%3}, [%4];"
                    : "=r"(a[fm][0]), "=r"(a[fm][1]), "=r"(a[fm][2]), "=r"(a[fm][3])
                    : "r"(addr));
            }
            uint32_t bf2[8][2];
#pragma unroll
            for (int fn = 0; fn < 8; fn++) {
                int t = wn * 64 + fn * 8 + g8;
                int ulo = 2 * k16, uhi = 2 * k16 + 1;
                uint32_t base = bBuf + t * 128 + tg * 4;
                uint32_t a0 = base + ((ulo ^ (t & 7)) << 4);
                uint32_t a1 = base + ((uhi ^ (t & 7)) << 4);
                asm volatile("ld.shared.b32 %0, [%1];" : "=r"(bf2[fn][0]) : "r"(a0));
                asm volatile("ld.shared.b32 %0, [%1];" : "=r"(bf2[fn][1]) : "r"(a1));
            }
#pragma unroll
            for (int fm = 0; fm < 4; fm++)
#pragma unroll
                for (int fn = 0; fn < 8; fn++) {
                    asm volatile(
                        "mma.sync.aligned.m16n8k16.row.col.f32.f16.f16.f32 "
                        "{%0,%1,%2,%3}, {%4,%5,%6,%7}, {%8,%9}, {%0,%1,%2,%3};"
                        : "+f"(acc[fm][fn][0]), "+f"(acc[fm][fn][1]),
                          "+f"(acc[fm][fn][2]), "+f"(acc[fm][fn][3])
                        : "r"(a[fm][0]), "r"(a[fm][1]), "r"(a[fm][2]), "r"(a[fm][3]),
                          "r"(bf2[fn][0]), "r"(bf2[fn][1]));
                }
        }
        __syncthreads();
        if (kk == 0) load_chunk(3, 0);
    }

    // ---- epilogue: M[bf][o][t] fp16 ----
    __half* Mb = g_M + (size_t)bf * OQ * 1024;
#pragma unroll
    for (int fm = 0; fm < 4; fm++)
#pragma unroll
        for (int fn = 0; fn < 8; fn++) {
            int o = o0 + wm * 64 + fm * 16 + g8;
            int t = t0 + wn * 64 + fn * 8 + tg * 2;
            __half2 lo = __floats2half2_rn(acc[fm][fn][0], acc[fm][fn][1]);
            __half2 hi = __floats2half2_rn(acc[fm][fn][2], acc[fm][fn][3]);
            *(__half2*)(Mb + (size_t)o * 1024 + t) = lo;
            *(__half2*)(Mb + (size_t)(o + 8) * 1024 + t) = hi;
        }
}

// ---------------------------------------------------------------------------
// Kernel 6: output transform. block = (b*256+o), 256 threads, 4 tiles each.
// ---------------------------------------------------------------------------
__global__ __launch_bounds__(256) void k_out(float* __restrict__ out) {
    int bo = blockIdx.x;           // b*256+o
    int b  = bo >> 8;
    int o  = bo & 255;
    const __half* Mb = g_M + ((size_t)(b * 16) * OQ + o) * 1024;   // +f*OQ*1024
    float* ob = out + (size_t)bo * (HQ * WQ);

#pragma unroll
    for (int k = 0; k < 4; k++) {
        int t = threadIdx.x + k * 256;
        float m[4][4];
#pragma unroll
        for (int f = 0; f < 16; f++)
            m[f >> 2][f & 3] = __half2float(Mb[(size_t)f * OQ * 1024 + t]);
        float T0[4], T1[4];
#pragma unroll
        for (int j = 0; j < 4; j++) {
            T0[j] = m[0][j] + m[1][j] + m[2][j];
            T1[j] = m[1][j] - m[2][j] - m[3][j];
        }
        float o00 = T0[0] + T0[1] + T0[2];
        float o01 = T0[1] - T0[2] - T0[3];
        float o10 = T1[0] + T1[1] + T1[2];
        float o11 = T1[1] - T1[2] - T1[3];
        int ty = t >> 5, tx = t & 31;
        float* d0 = ob + (2 * ty) * WQ + 2 * tx;
        *(float2*)d0          = make_float2(o00, o01);
        *(float2*)(d0 + WQ)   = make_float2(o10, o11);
    }
}

// ---------------------------------------------------------------------------
extern "C" void kernel_launch(void* const* d_in, const int* in_sizes, int n_in,
                              void* d_out, int out_size) {
    const float* q       = (const float*)d_in[0];
    const float* y       = (const float*)d_in[1];
    const float* experts = (const float*)d_in[2];
    const float* gate_w  = (const float*)d_in[3];
    const float* gate_b  = (const float*)d_in[4];
    float* out = (float*)d_out;

    cudaFuncSetAttribute(k_trans, cudaFuncAttributeMaxDynamicSharedMemorySize, TQ_SMEM);
    cudaFuncSetAttribute(k_wgemm, cudaFuncAttributeMaxDynamicSharedMemorySize, WG_SMEM);

    k_mean<<<BQ * CQ, 256>>>(y);
    k_gates<<<BQ, 256>>>(gate_w, gate_b);
    k_trans<<<dim3(32, BQ), 256, TQ_SMEM>>>(q);     // independent of gates
    k_foldU<<<OQ, 256>>>(experts);
    k_wgemm<<<dim3(8, 2, BQ * 16), 128, WG_SMEM>>>();
    k_out<<<BQ * OQ, 256>>>(out);
}

// round 11
// speedup vs baseline: 1.0731x; 1.0731x over previous
#include <cuda_runtime.h>
#include <cuda_fp16.h>
#include <cstdint>

// Problem: B=8, C=256, H=W=64, O=256, K=3, E=3
// Winograd F(2x2,3x3) with FUSED output transform:
//   U[b][f][o][c] = G w2 G^T    (fp16)
//   V[b][f][t][c] = B^T d B     (fp16)
//   per CTA (64o x 64t): loop f=0..15 { M_f = U_f V_f^T (fp32 acc);
//       out_acc += (AT[i][fr]*AT[j][fc]) * M_f }  -> write out directly.
// No g_M intermediate (saves 134MB DRAM vs R9).

#define BQ 8
#define CQ 256
#define HQ 64
#define WQ 64
#define OQ 256

__device__ float  g_yctx[BQ * CQ];
__device__ float  g_gates[BQ * 3];
__device__ __half g_U[(size_t)BQ * 16 * OQ * CQ];       // [b][f][o][c]
__device__ __half g_V[(size_t)BQ * 16 * 1024 * CQ];     // [b][f][t][c]

__device__ __forceinline__ uint32_t smem_u32(const void* p) {
    uint32_t a;
    asm("{ .reg .u64 t; cvta.to.shared.u64 t, %1; cvt.u32.u64 %0, t; }" : "=r"(a) : "l"(p));
    return a;
}

// ---------------------------------------------------------------------------
// Kernel 1: global average pool of y -> g_yctx
// ---------------------------------------------------------------------------
__global__ void k_mean(const float* __restrict__ y) {
    int bc = blockIdx.x;
    const float* p = y + (size_t)bc * (HQ * WQ);
    float s = 0.f;
    for (int i = threadIdx.x; i < HQ * WQ; i += 256) s += p[i];
    __shared__ float sm[256];
    sm[threadIdx.x] = s;
    __syncthreads();
    for (int st = 128; st > 0; st >>= 1) {
        if (threadIdx.x < st) sm[threadIdx.x] += sm[threadIdx.x + st];
        __syncthreads();
    }
    if (threadIdx.x == 0) g_yctx[bc] = sm[0] * (1.f / (HQ * WQ));
}

// ---------------------------------------------------------------------------
// Kernel 2: softmax gates
// ---------------------------------------------------------------------------
__global__ void k_gates(const float* __restrict__ gw, const float* __restrict__ gb) {
    int b = blockIdx.x;
    int c = threadIdx.x;
    float v = g_yctx[b * CQ + c];
    float p0 = v * (gw[c * 3 + 0] + gw[(c + CQ) * 3 + 0]);
    float p1 = v * (gw[c * 3 + 1] + gw[(c + CQ) * 3 + 1]);
    float p2 = v * (gw[c * 3 + 2] + gw[(c + CQ) * 3 + 2]);
    __shared__ float sm[3][256];
    sm[0][c] = p0; sm[1][c] = p1; sm[2][c] = p2;
    __syncthreads();
    for (int st = 128; st > 0; st >>= 1) {
        if (c < st) {
            sm[0][c] += sm[0][c + st];
            sm[1][c] += sm[1][c + st];
            sm[2][c] += sm[2][c + st];
        }
        __syncthreads();
    }
    if (c == 0) {
        float l0 = sm[0][0] + gb[0], l1 = sm[1][0] + gb[1], l2 = sm[2][0] + gb[2];
        float m = fmaxf(l0, fmaxf(l1, l2));
        float e0 = expf(l0 - m), e1 = expf(l1 - m), e2 = expf(l2 - m);
        float inv = 1.f / (e0 + e1 + e2);
        g_gates[b * 3 + 0] = e0 * inv;
        g_gates[b * 3 + 1] = e1 * inv;
        g_gates[b * 3 + 2] = e2 * inv;
    }
}

// ---------------------------------------------------------------------------
// Kernel 3: fold experts + Winograd weight transform -> U[b][f][o][c] fp16
// ---------------------------------------------------------------------------
__global__ void k_foldU(const float* __restrict__ experts) {
    int o = blockIdx.x;
    int c = threadIdx.x;
    const size_t ES = (size_t)OQ * (2 * CQ) * 9;
    float f3[3][9];
#pragma unroll
    for (int e = 0; e < 3; e++) {
        const float* p = experts + e * ES + (size_t)o * (2 * CQ * 9) + (size_t)c * 9;
#pragma unroll
        for (int t = 0; t < 9; t++) f3[e][t] = p[t] + p[CQ * 9 + t];
    }
#pragma unroll
    for (int b = 0; b < BQ; b++) {
        float g0 = g_gates[b * 3 + 0];
        float g1 = g_gates[b * 3 + 1];
        float g2 = g_gates[b * 3 + 2];
        float w[3][3];
#pragma unroll
        for (int t = 0; t < 9; t++)
            w[t / 3][t % 3] = g0 * f3[0][t] + g1 * f3[1][t] + g2 * f3[2][t];
        float T[4][3];
#pragma unroll
        for (int j = 0; j < 3; j++) {
            T[0][j] = w[0][j];
            T[1][j] = 0.5f * (w[0][j] + w[1][j] + w[2][j]);
            T[2][j] = 0.5f * (w[0][j] - w[1][j] + w[2][j]);
            T[3][j] = w[2][j];
        }
        __half* ub = g_U + ((size_t)b * 16 * OQ + o) * CQ + c;
#pragma unroll
        for (int r = 0; r < 4; r++) {
            float u0 = T[r][0];
            float u1 = 0.5f * (T[r][0] + T[r][1] + T[r][2]);
            float u2 = 0.5f * (T[r][0] - T[r][1] + T[r][2]);
            float u3 = T[r][2];
            ub[(size_t)(r * 4 + 0) * OQ * CQ] = __float2half_rn(u0);
            ub[(size_t)(r * 4 + 1) * OQ * CQ] = __float2half_rn(u1);
            ub[(size_t)(r * 4 + 2) * OQ * CQ] = __float2half_rn(u2);
            ub[(size_t)(r * 4 + 3) * OQ * CQ] = __float2half_rn(u3);
        }
    }
}

// ---------------------------------------------------------------------------
// Kernel 4: input transform q -> V[b][f][t][c] fp16 (unchanged from R9)
// ---------------------------------------------------------------------------
#define TQ_SQW 265
#define TQ_SQ_BYTES (32 * TQ_SQW * 4)
#define TQ_VT_OFF TQ_SQ_BYTES
#define TQ_SMEM (TQ_SQ_BYTES + 16 * 32 * 32 * 2)   // 66688

__global__ __launch_bounds__(256) void k_trans(const float* __restrict__ q) {
    extern __shared__ __align__(16) unsigned char smt[];
    float*  sQ  = (float*)smt;
    __half* sVt = (__half*)(smt + TQ_VT_OFF);

    int ty = blockIdx.x;
    int b  = blockIdx.y;
    int tid = threadIdx.x;

    const float* qb = q + (size_t)b * CQ * HQ * WQ;

    for (int cc = 0; cc < 8; cc++) {
        int c0 = cc * 32;
        __syncthreads();

        for (int i = tid; i < 32 * 264; i += 256) {
            int c   = i / 264;
            int rem = i - c * 264;
            int r   = rem / 66;
            int x   = rem - r * 66 - 1;
            int gy  = 2 * ty - 1 + r;
            float v = 0.f;
            if ((unsigned)gy < (unsigned)HQ && (unsigned)x < (unsigned)WQ)
                v = qb[(size_t)(c0 + c) * (HQ * WQ) + gy * WQ + x];
            sQ[c * TQ_SQW + rem] = v;
        }
        __syncthreads();

#pragma unroll
        for (int jj = 0; jj < 4; jj++) {
            int j  = jj * 256 + tid;
            int c  = j & 31;
            int tx = j >> 5;
            const float* dp = sQ + c * TQ_SQW + 2 * tx;
            float d[4][4];
#pragma unroll
            for (int r = 0; r < 4; r++)
#pragma unroll
                for (int jx = 0; jx < 4; jx++)
                    d[r][jx] = dp[r * 66 + jx];
            float T[4][4];
#pragma unroll
            for (int jx = 0; jx < 4; jx++) {
                T[0][jx] = d[0][jx] - d[2][jx];
                T[1][jx] = d[1][jx] + d[2][jx];
                T[2][jx] = d[2][jx] - d[1][jx];
                T[3][jx] = d[1][jx] - d[3][jx];
            }
#pragma unroll
            for (int r = 0; r < 4; r++) {
                float v0 = T[r][0] - T[r][2];
                float v1 = T[r][1] + T[r][2];
                float v2 = T[r][2] - T[r][1];
                float v3 = T[r][1] - T[r][3];
                sVt[((r * 4 + 0) * 32 + tx) * 32 + c] = __float2half_rn(v0);
                sVt[((r * 4 + 1) * 32 + tx) * 32 + c] = __float2half_rn(v1);
                sVt[((r * 4 + 2) * 32 + tx) * 32 + c] = __float2half_rn(v2);
                sVt[((r * 4 + 3) * 32 + tx) * 32 + c] = __float2half_rn(v3);
            }
        }
        __syncthreads();

#pragma unroll
        for (int k = 0; k < 8; k++) {
            int u   = tid + k * 256;
            int f   = u >> 7;
            int rem = u & 127;
            int tx  = rem >> 2;
            int uq  = rem & 3;
            uint4 v = *(const uint4*)(sVt + (f * 32 + tx) * 32 + uq * 8);
            __half* dst = g_V + (((size_t)(b * 16 + f) * 1024) + ty * 32 + tx) * CQ
                        + c0 + uq * 8;
            *(uint4*)dst = v;
        }
    }
}

// ---------------------------------------------------------------------------
// Kernel 5: FUSED GEMM + output transform.
// grid (16 tblk, 4 oblk, b). CTA 64o x 64t, 4 warps (2Mx2N), warp 32x32.
// 64-stage pipeline (16 f x 4 k-chunks of 64c), 3 buffers x 16KB.
// ---------------------------------------------------------------------------
#define FW_STG   16384                   // A 8192 + B 8192
#define FW_SMEM  (3 * FW_STG)            // 49152

__global__ __launch_bounds__(128, 2)
void k_fwino(float* __restrict__ out) {
    extern __shared__ __align__(16) unsigned char smg[];
    const uint32_t sb = smem_u32(smg);

    int tid  = threadIdx.x;
    int lane = tid & 31;
    int warp = tid >> 5;
    int wm   = warp >> 1;       // 0..1 (32 o rows)
    int wn   = warp & 1;        // 0..1 (32 t cols)

    int t0 = blockIdx.x * 64;
    int o0 = blockIdx.y * 64;
    int b  = blockIdx.z;
    int b16 = b * 16;

    int tg = lane & 3;
    int g8 = lane >> 2;

    // out accumulators: [fm][fn][k][p], p = 2x2 pixel
    float oa[2][4][4][4];
#pragma unroll
    for (int i = 0; i < 2; i++)
#pragma unroll
        for (int j = 0; j < 4; j++)
#pragma unroll
            for (int k = 0; k < 4; k++)
#pragma unroll
                for (int p = 0; p < 4; p++) oa[i][j][k][p] = 0.f;

    auto load_stage = [&](int s) {
        int f = s >> 2, kk = s & 3;
        const __half* Af = g_U + (((size_t)(b16 + f) * OQ) + o0) * CQ + kk * 64;
        const __half* Bf = g_V + (((size_t)(b16 + f) * 1024) + t0) * CQ + kk * 64;
        uint32_t stg = sb + (s % 3) * FW_STG;
#pragma unroll
        for (int g = 0; g < 8; g++) {
            int idx  = tid + g * 128;     // 0..1023
            int part = idx >> 9;
            int rem  = idx & 511;
            int row  = rem >> 3;
            int u    = rem & 7;
            const __half* src = (part ? Bf : Af) + (size_t)row * CQ + u * 8;
            uint32_t dst = stg + part * 8192 + row * 128 + ((u ^ (row & 7)) << 4);
            asm volatile("cp.async.cg.shared.global [%0], [%1], 16;"
                         :: "r"(dst), "l"(src));
        }
        asm volatile("cp.async.commit_group;");
    };

    load_stage(0);
    load_stage(1);

    int s = 0;
    for (int f = 0; f < 16; f++) {
        float acc[2][4][4];
#pragma unroll
        for (int i = 0; i < 2; i++)
#pragma unroll
            for (int j = 0; j < 4; j++)
#pragma unroll
                for (int k = 0; k < 4; k++) acc[i][j][k] = 0.f;

        for (int kk = 0; kk < 4; kk++, s++) {
            if (s + 2 < 64) load_stage(s + 2);
            if (s < 62)      asm volatile("cp.async.wait_group 2;");
            else if (s == 62) asm volatile("cp.async.wait_group 1;");
            else              asm volatile("cp.async.wait_group 0;");
            __syncthreads();

            uint32_t aBuf = sb + (s % 3) * FW_STG;
            uint32_t bBuf = aBuf + 8192;

#pragma unroll
            for (int k16 = 0; k16 < 4; k16++) {
                uint32_t a[2][4];
#pragma unroll
                for (int fm = 0; fm < 2; fm++) {
                    int row = wm * 32 + fm * 16 + (lane & 15);
                    int u   = (lane >> 4) + 2 * k16;
                    uint32_t addr = aBuf + row * 128 + ((u ^ (row & 7)) << 4);
                    asm volatile(
                        "ldmatrix.sync.aligned.m8n8.x4.shared.b16 {%0,%1,%2,%3}, [%4];"
                        : "=r"(a[fm][0]), "=r"(a[fm][1]), "=r"(a[fm][2]), "=r"(a[fm][3])
                        : "r"(addr));
                }
                uint32_t bf2[4][2];
#pragma unroll
                for (int fn = 0; fn < 4; fn++) {
                    int t = wn * 32 + fn * 8 + g8;
                    uint32_t base = bBuf + t * 128 + tg * 4;
                    uint32_t a0 = base + (((2 * k16)     ^ (t & 7)) << 4);
                    uint32_t a1 = base + (((2 * k16 + 1) ^ (t & 7)) << 4);
                    asm volatile("ld.shared.b32 %0, [%1];" : "=r"(bf2[fn][0]) : "r"(a0));
                    asm volatile("ld.shared.b32 %0, [%1];" : "=r"(bf2[fn][1]) : "r"(a1));
                }
#pragma unroll
                for (int fm = 0; fm < 2; fm++)
#pragma unroll
                    for (int fn = 0; fn < 4; fn++) {
                        asm volatile(
                            "mma.sync.aligned.m16n8k16.row.col.f32.f16.f16.f32 "
                            "{%0,%1,%2,%3}, {%4,%5,%6,%7}, {%8,%9}, {%0,%1,%2,%3};"
                            : "+f"(acc[fm][fn][0]), "+f"(acc[fm][fn][1]),
                              "+f"(acc[fm][fn][2]), "+f"(acc[fm][fn][3])
                            : "r"(a[fm][0]), "r"(a[fm][1]), "r"(a[fm][2]), "r"(a[fm][3]),
                              "r"(bf2[fn][0]), "r"(bf2[fn][1]));
                    }
            }
            __syncthreads();
        }

        // ---- fold M_f into output accumulators ----
        int fr = f >> 2, fc = f & 3;
        float ar0 = (fr == 3) ? 0.f : 1.f;
        float ar1 = (fr == 0) ? 0.f : ((fr == 1) ? 1.f : -1.f);
        float ac0 = (fc == 3) ? 0.f : 1.f;
        float ac1 = (fc == 0) ? 0.f : ((fc == 1) ? 1.f : -1.f);
        float c00 = ar0 * ac0, c01 = ar0 * ac1, c10 = ar1 * ac0, c11 = ar1 * ac1;
#pragma unroll
        for (int fm = 0; fm < 2; fm++)
#pragma unroll
            for (int fn = 0; fn < 4; fn++)
#pragma unroll
                for (int k = 0; k < 4; k++) {
                    float m = acc[fm][fn][k];
                    oa[fm][fn][k][0] += c00 * m;
                    oa[fm][fn][k][1] += c01 * m;
                    oa[fm][fn][k][2] += c10 * m;
                    oa[fm][fn][k][3] += c11 * m;
                }
    }

    // ---- epilogue: scatter 2x2 outputs ----
#pragma unroll
    for (int fm = 0; fm < 2; fm++)
#pragma unroll
        for (int fn = 0; fn < 4; fn++)
#pragma unroll
            for (int kh = 0; kh < 2; kh++) {
                int o = o0 + wm * 32 + fm * 16 + g8 + kh * 8;
                int t = t0 + wn * 32 + fn * 8 + tg * 2;
                int ty = t >> 5, tx = t & 31;
                float* ob = out + ((size_t)(b * OQ + o) * HQ + 2 * ty) * WQ + 2 * tx;
                int k0 = kh * 2, k1 = kh * 2 + 1;
                float4 r0 = make_float4(oa[fm][fn][k0][0], oa[fm][fn][k0][1],
                                        oa[fm][fn][k1][0], oa[fm][fn][k1][1]);
                float4 r1 = make_float4(oa[fm][fn][k0][2], oa[fm][fn][k0][3],
                                        oa[fm][fn][k1][2], oa[fm][fn][k1][3]);
                *(float4*)ob        = r0;
                *(float4*)(ob + WQ) = r1;
            }
}

// ---------------------------------------------------------------------------
extern "C" void kernel_launch(void* const* d_in, const int* in_sizes, int n_in,
                              void* d_out, int out_size) {
    const float* q       = (const float*)d_in[0];
    const float* y       = (const float*)d_in[1];
    const float* experts = (const float*)d_in[2];
    const float* gate_w  = (const float*)d_in[3];
    const float* gate_b  = (const float*)d_in[4];
    float* out = (float*)d_out;

    cudaFuncSetAttribute(k_trans, cudaFuncAttributeMaxDynamicSharedMemorySize, TQ_SMEM);
    cudaFuncSetAttribute(k_fwino, cudaFuncAttributeMaxDynamicSharedMemorySize, FW_SMEM);

    k_mean<<<BQ * CQ, 256>>>(y);
    k_gates<<<BQ, 256>>>(gate_w, gate_b);
    k_trans<<<dim3(32, BQ), 256, TQ_SMEM>>>(q);
    k_foldU<<<OQ, 256>>>(experts);
    k_fwino<<<dim3(16, 4, BQ), 128, FW_SMEM>>>(out);
}